// round 10
// baseline (speedup 1.0000x reference)
#include <cuda_runtime.h>
#include <cuda_bf16.h>
#include <cuda_fp16.h>

#define T_DIM 64
#define B_DIM 16
#define S_DIM 256
#define D_DIM 512
#define T_TILE 2       // t-rows per logits block
#define T_AV   8       // t-rows per AV block

// scratch: h = input @ W_comb + b_comb as half, stored (B, T, D)
__device__ __half2 g_h16[B_DIM * T_DIM * D_DIM / 2];
// scratch: context converted to half, (B, S, D)
__device__ __half2 g_c16[B_DIM * S_DIM * D_DIM / 2];

__device__ __forceinline__ __half2 tanh2_ap(__half2 x) {
    unsigned xi = *(unsigned*)&x;
    unsigned yi;
    asm("tanh.approx.f16x2 %0, %1;" : "=r"(yi) : "r"(xi));
    return *(__half2*)&yi;
}

// ---------------------------------------------------------------------------
// Kernel 0: convert context fp32 -> half2. 2.1M floats, 8 per thread.
// ---------------------------------------------------------------------------
__global__ __launch_bounds__(256) void conv_kernel(const float* __restrict__ src)
{
    const int i = blockIdx.x * 256 + threadIdx.x;
    const float4 a = ((const float4*)src)[2 * i];
    const float4 b = ((const float4*)src)[2 * i + 1];
    __half2 out[4];
    out[0] = __floats2half2_rn(a.x, a.y);
    out[1] = __floats2half2_rn(a.z, a.w);
    out[2] = __floats2half2_rn(b.x, b.y);
    out[3] = __floats2half2_rn(b.z, b.w);
    ((uint4*)g_c16)[i] = *(const uint4*)out;
}

// ---------------------------------------------------------------------------
// Kernel 1: h = input @ W + bias (M=1024,N=512,K=512), writes half2 g_h16.
// R5-proven: 64x64 tile, 256 thr, 4x4 microtile, double-buffered SMEM.
// ---------------------------------------------------------------------------
__global__ __launch_bounds__(256, 2) void gemm_kernel(
    const float* __restrict__ A,
    const float* __restrict__ W,
    const float* __restrict__ bias)
{
    __shared__ float As[2][64][33];
    __shared__ float Bs[2][32][68];

    const int tid = threadIdx.x;
    const int tx = tid & 15;
    const int ty = tid >> 4;
    const int m0 = blockIdx.y * 64;
    const int n0 = blockIdx.x * 64;

    const int ar0 = tid >> 3,         ac0 = (tid & 7) * 4;
    const int ar1 = (tid + 256) >> 3, ac1 = ((tid + 256) & 7) * 4;
    const int br0 = tid >> 4,         bc0 = (tid & 15) * 4;
    const int br1 = (tid + 256) >> 4, bc1 = ((tid + 256) & 15) * 4;

    float acc[4][4];
#pragma unroll
    for (int i = 0; i < 4; ++i)
#pragma unroll
        for (int j = 0; j < 4; ++j) acc[i][j] = 0.f;

    {
        float4 a0 = *(const float4*)&A[(size_t)(m0 + ar0) * D_DIM + ac0];
        float4 a1 = *(const float4*)&A[(size_t)(m0 + ar1) * D_DIM + ac1];
        float4 b0 = *(const float4*)&W[(size_t)br0 * D_DIM + n0 + bc0];
        float4 b1 = *(const float4*)&W[(size_t)br1 * D_DIM + n0 + bc1];
        As[0][ar0][ac0 + 0] = a0.x; As[0][ar0][ac0 + 1] = a0.y;
        As[0][ar0][ac0 + 2] = a0.z; As[0][ar0][ac0 + 3] = a0.w;
        As[0][ar1][ac1 + 0] = a1.x; As[0][ar1][ac1 + 1] = a1.y;
        As[0][ar1][ac1 + 2] = a1.z; As[0][ar1][ac1 + 3] = a1.w;
        *(float4*)&Bs[0][br0][bc0] = b0;
        *(float4*)&Bs[0][br1][bc1] = b1;
    }
    __syncthreads();

    int buf = 0;
    for (int k0 = 0; k0 < D_DIM; k0 += 32) {
        const bool has_next = (k0 + 32) < D_DIM;
        float4 a0, a1, b0, b1;
        if (has_next) {
            const int kn = k0 + 32;
            a0 = *(const float4*)&A[(size_t)(m0 + ar0) * D_DIM + kn + ac0];
            a1 = *(const float4*)&A[(size_t)(m0 + ar1) * D_DIM + kn + ac1];
            b0 = *(const float4*)&W[(size_t)(kn + br0) * D_DIM + n0 + bc0];
            b1 = *(const float4*)&W[(size_t)(kn + br1) * D_DIM + n0 + bc1];
        }

#pragma unroll
        for (int k = 0; k < 32; ++k) {
            float4 b4 = *(const float4*)&Bs[buf][k][tx * 4];
            float x0 = As[buf][ty * 4 + 0][k];
            float x1 = As[buf][ty * 4 + 1][k];
            float x2 = As[buf][ty * 4 + 2][k];
            float x3 = As[buf][ty * 4 + 3][k];
            acc[0][0] += x0 * b4.x; acc[0][1] += x0 * b4.y; acc[0][2] += x0 * b4.z; acc[0][3] += x0 * b4.w;
            acc[1][0] += x1 * b4.x; acc[1][1] += x1 * b4.y; acc[1][2] += x1 * b4.z; acc[1][3] += x1 * b4.w;
            acc[2][0] += x2 * b4.x; acc[2][1] += x2 * b4.y; acc[2][2] += x2 * b4.z; acc[2][3] += x2 * b4.w;
            acc[3][0] += x3 * b4.x; acc[3][1] += x3 * b4.y; acc[3][2] += x3 * b4.z; acc[3][3] += x3 * b4.w;
        }

        if (has_next) {
            const int nb = buf ^ 1;
            As[nb][ar0][ac0 + 0] = a0.x; As[nb][ar0][ac0 + 1] = a0.y;
            As[nb][ar0][ac0 + 2] = a0.z; As[nb][ar0][ac0 + 3] = a0.w;
            As[nb][ar1][ac1 + 0] = a1.x; As[nb][ar1][ac1 + 1] = a1.y;
            As[nb][ar1][ac1 + 2] = a1.z; As[nb][ar1][ac1 + 3] = a1.w;
            *(float4*)&Bs[nb][br0][bc0] = b0;
            *(float4*)&Bs[nb][br1][bc1] = b1;
        }
        __syncthreads();
        buf ^= 1;
    }

#pragma unroll
    for (int i = 0; i < 4; ++i) {
        int m = m0 + ty * 4 + i;
        int bb = m & (B_DIM - 1);
        int tt = m >> 4;
        const float b0 = bias[n0 + tx * 4 + 0];
        const float b1 = bias[n0 + tx * 4 + 1];
        const float b2 = bias[n0 + tx * 4 + 2];
        const float b3 = bias[n0 + tx * 4 + 3];
        __half2 h2[2];
        h2[0] = __floats2half2_rn(acc[i][0] + b0, acc[i][1] + b1);
        h2[1] = __floats2half2_rn(acc[i][2] + b2, acc[i][3] + b3);
        __half2* dst = &g_h16[(((size_t)bb * T_DIM + tt) * D_DIM + n0 + tx * 4) / 2];
        *(uint2*)dst = *(const uint2*)h2;
    }
}

// ---------------------------------------------------------------------------
// Kernel 2: logits + softmax. grid=(B, T/2)=512 blocks, 512 thr, 2 CTA/SM.
// Warp w owns full D (16 dims/lane as 8 half2) and 16 s values (s=w*16..+15).
// No packing in loop; 6 shfl per s for both t's; softmax by warps 0..1.
// ---------------------------------------------------------------------------
__global__ __launch_bounds__(512, 2) void logits_kernel(
    const float* __restrict__ v_w,       // (D) fp32
    float* __restrict__ out_attn)        // (B*T, S) -> normalized probs
{
    __shared__ float lg[T_TILE][S_DIM];  // 2 KB

    const int b    = blockIdx.x;
    const int t0   = blockIdx.y * T_TILE;
    const int tid  = threadIdx.x;
    const int wid  = tid >> 5;
    const int lane = tid & 31;

    // register-resident h (2 t x 8 half2) and vw (8 half2); lane owns dims [16*lane,16*lane+16)
    __half2 hh[T_TILE][8];
    __half2 ww[8];
    {
        const uint4* hp = (const uint4*)(g_h16 + ((size_t)b * T_DIM + t0) * (D_DIM / 2));
#pragma unroll
        for (int t = 0; t < T_TILE; ++t) {
            uint4 u0 = hp[t * (D_DIM / 8) + lane * 2];
            uint4 u1 = hp[t * (D_DIM / 8) + lane * 2 + 1];
            *(uint4*)&hh[t][0] = u0;
            *(uint4*)&hh[t][4] = u1;
        }
        const float4* vw4 = (const float4*)v_w;
#pragma unroll
        for (int j = 0; j < 4; ++j) {
            float4 w = vw4[lane * 4 + j];
            ww[j * 2 + 0] = __floats2half2_rn(w.x, w.y);
            ww[j * 2 + 1] = __floats2half2_rn(w.z, w.w);
        }
    }

    // s loop: warp wid handles s = wid*16 .. wid*16+15
    {
        const uint4* cbase = (const uint4*)(g_c16 + (size_t)b * S_DIM * (D_DIM / 2))
                             + (size_t)(wid * 16) * (D_DIM / 8) + lane * 2;
        uint4 cu0 = cbase[0];
        uint4 cu1 = cbase[1];

        for (int si = 0; si < 16; ++si) {
            uint4 nu0, nu1;
            if (si < 15) {
                nu0 = cbase[(si + 1) * (D_DIM / 8)];
                nu1 = cbase[(si + 1) * (D_DIM / 8) + 1];
            }
            __half2 cc[8];
            *(uint4*)&cc[0] = cu0;
            *(uint4*)&cc[4] = cu1;

            float acc[T_TILE];
#pragma unroll
            for (int t = 0; t < T_TILE; ++t) {
                __half2 p[8];
#pragma unroll
                for (int j = 0; j < 8; ++j)
                    p[j] = __hmul2(tanh2_ap(__hadd2(hh[t][j], cc[j])), ww[j]);
                __half2 q0 = __hadd2(p[0], p[1]);
                __half2 q1 = __hadd2(p[2], p[3]);
                __half2 q2 = __hadd2(p[4], p[5]);
                __half2 q3 = __hadd2(p[6], p[7]);
                float a = (__low2float(q0) + __high2float(q0))
                        + (__low2float(q1) + __high2float(q1));
                float c = (__low2float(q2) + __high2float(q2))
                        + (__low2float(q3) + __high2float(q3));
                acc[t] = a + c;
            }

            // merged reduction for 2 accumulators: 6 shfl
            float r0 = acc[0] + __shfl_xor_sync(0xffffffffu, acc[0], 16);
            float r1 = acc[1] + __shfl_xor_sync(0xffffffffu, acc[1], 16);
            float m = (lane & 16) ? r1 : r0;   // lanes 0-15: t0, lanes 16-31: t1
            m += __shfl_xor_sync(0xffffffffu, m, 8);
            m += __shfl_xor_sync(0xffffffffu, m, 4);
            m += __shfl_xor_sync(0xffffffffu, m, 2);
            m += __shfl_xor_sync(0xffffffffu, m, 1);
            if ((lane & 15) == 0)
                lg[lane >> 4][wid * 16 + si] = m;

            cu0 = nu0; cu1 = nu1;
        }
    }
    __syncthreads();

    // ---- softmax: warps 0..1, row t = wid (v_b cancels) ----
    if (wid < T_TILE) {
        const int t = wid;
        float e[8];
        float m = -1e30f;
#pragma unroll
        for (int k = 0; k < 8; ++k) {
            e[k] = lg[t][k * 32 + lane];
            m = fmaxf(m, e[k]);
        }
#pragma unroll
        for (int o = 16; o; o >>= 1) m = fmaxf(m, __shfl_xor_sync(0xffffffffu, m, o));
        float ssum = 0.f;
#pragma unroll
        for (int k = 0; k < 8; ++k) {
            e[k] = __expf(e[k] - m);
            ssum += e[k];
        }
#pragma unroll
        for (int o = 16; o; o >>= 1) ssum += __shfl_xor_sync(0xffffffffu, ssum, o);
        const float inv = 1.0f / ssum;
        float* oa = out_attn + ((size_t)b * T_DIM + t0 + t) * S_DIM;
#pragma unroll
        for (int k = 0; k < 8; ++k)
            oa[k * 32 + lane] = e[k] * inv;
    }
}

// ---------------------------------------------------------------------------
// Kernel 3: weighted = attn @ values. grid=(B, 2, T/8)=256 blocks, 256 thr.
// ---------------------------------------------------------------------------
__global__ __launch_bounds__(256) void av_kernel(
    const float* __restrict__ values,    // (B,S,D)
    const float* __restrict__ attn,      // (B*T, S) normalized
    float* __restrict__ out_w)           // (T,B,D)
{
    __shared__ float p_s[T_AV][S_DIM];   // 8 KB

    const int b   = blockIdx.x;
    const int dh  = blockIdx.y;
    const int t0  = blockIdx.z * T_AV;
    const int tid = threadIdx.x;

    {
        const float4* ap = (const float4*)(attn + ((size_t)b * T_DIM + t0) * S_DIM);
        float4* ps4 = (float4*)p_s;
        for (int i = tid; i < T_AV * S_DIM / 4; i += 256) ps4[i] = ap[i];
    }
    __syncthreads();

    const int d = dh * 256 + tid;
    const float* vp = values + (size_t)b * S_DIM * D_DIM + d;

    float w[T_AV];
#pragma unroll
    for (int t = 0; t < T_AV; ++t) w[t] = 0.f;

    float v0 = vp[0 * D_DIM];
    float v1 = vp[1 * D_DIM];
    float v2 = vp[2 * D_DIM];
    float v3 = vp[3 * D_DIM];

    for (int s = 0; s < S_DIM; s += 4) {
        float n0, n1, n2, n3;
        if (s + 4 < S_DIM) {
            n0 = vp[(size_t)(s + 4) * D_DIM];
            n1 = vp[(size_t)(s + 5) * D_DIM];
            n2 = vp[(size_t)(s + 6) * D_DIM];
            n3 = vp[(size_t)(s + 7) * D_DIM];
        }
#pragma unroll
        for (int t = 0; t < T_AV; ++t) {
            float4 p = *(const float4*)&p_s[t][s];
            w[t] += p.x * v0 + p.y * v1 + p.z * v2 + p.w * v3;
        }
        v0 = n0; v1 = n1; v2 = n2; v3 = n3;
    }

#pragma unroll
    for (int t = 0; t < T_AV; ++t)
        out_w[((size_t)(t0 + t) * B_DIM + b) * D_DIM + d] = w[t];
}

// ---------------------------------------------------------------------------
extern "C" void kernel_launch(void* const* d_in, const int* in_sizes, int n_in,
                              void* d_out, int out_size) {
    const float* input   = (const float*)d_in[0];
    const float* context = (const float*)d_in[1];
    const float* values  = (const float*)d_in[2];
    const float* W_comb  = (const float*)d_in[3];
    const float* b_comb  = (const float*)d_in[4];
    const float* v_w     = (const float*)d_in[5];

    float* out_weighted = (float*)d_out;                                 // (T,B,D)
    float* out_attn     = (float*)d_out + (size_t)T_DIM * B_DIM * D_DIM; // (B*T,S)

    const int conv_blocks = (B_DIM * S_DIM * D_DIM / 8) / 256;           // 1024
    conv_kernel<<<conv_blocks, 256>>>(context);

    dim3 g1(D_DIM / 64, (T_DIM * B_DIM) / 64);           // (8,16)
    gemm_kernel<<<g1, 256>>>(input, W_comb, b_comb);

    dim3 g2(B_DIM, T_DIM / T_TILE);                      // (16,32) = 512 blocks
    logits_kernel<<<g2, 512>>>(v_w, out_attn);

    dim3 g3(B_DIM, 2, T_DIM / T_AV);                     // (16,2,8) = 256 blocks
    av_kernel<<<g3, 256>>>(values, out_attn, out_weighted);
}

// round 11
// speedup vs baseline: 1.0047x; 1.0047x over previous
#include <cuda_runtime.h>
#include <cuda_bf16.h>
#include <cuda_fp16.h>

#define T_DIM 64
#define B_DIM 16
#define S_DIM 256
#define D_DIM 512
#define T_TILE 2       // t-rows per logits block
#define T_AV   8       // t-rows per AV block

// scratch: h = input @ W_comb + b_comb as half, stored (B, T, D)
__device__ __half2 g_h16[B_DIM * T_DIM * D_DIM / 2];
// scratch: context converted to half, (B, S, D)
__device__ __half2 g_c16[B_DIM * S_DIM * D_DIM / 2];

__device__ __forceinline__ __half2 tanh2_ap(__half2 x) {
    unsigned xi = *(unsigned*)&x;
    unsigned yi;
    asm("tanh.approx.f16x2 %0, %1;" : "=r"(yi) : "r"(xi));
    return *(__half2*)&yi;
}

// ---------------------------------------------------------------------------
// Kernel 0: convert context fp32 -> half2. 2.1M floats, 8 per thread.
// ---------------------------------------------------------------------------
__global__ __launch_bounds__(256) void conv_kernel(const float* __restrict__ src)
{
    const int i = blockIdx.x * 256 + threadIdx.x;
    const float4 a = ((const float4*)src)[2 * i];
    const float4 b = ((const float4*)src)[2 * i + 1];
    __half2 out[4];
    out[0] = __floats2half2_rn(a.x, a.y);
    out[1] = __floats2half2_rn(a.z, a.w);
    out[2] = __floats2half2_rn(b.x, b.y);
    out[3] = __floats2half2_rn(b.z, b.w);
    ((uint4*)g_c16)[i] = *(const uint4*)out;
}

// ---------------------------------------------------------------------------
// Kernel 1: h = input @ W + bias (M=1024,N=512,K=512), writes half2 g_h16.
// R5-proven: 64x64 tile, 256 thr, 4x4 microtile, double-buffered SMEM.
// ---------------------------------------------------------------------------
__global__ __launch_bounds__(256, 2) void gemm_kernel(
    const float* __restrict__ A,
    const float* __restrict__ W,
    const float* __restrict__ bias)
{
    __shared__ float As[2][64][33];
    __shared__ float Bs[2][32][68];

    const int tid = threadIdx.x;
    const int tx = tid & 15;
    const int ty = tid >> 4;
    const int m0 = blockIdx.y * 64;
    const int n0 = blockIdx.x * 64;

    const int ar0 = tid >> 3,         ac0 = (tid & 7) * 4;
    const int ar1 = (tid + 256) >> 3, ac1 = ((tid + 256) & 7) * 4;
    const int br0 = tid >> 4,         bc0 = (tid & 15) * 4;
    const int br1 = (tid + 256) >> 4, bc1 = ((tid + 256) & 15) * 4;

    float acc[4][4];
#pragma unroll
    for (int i = 0; i < 4; ++i)
#pragma unroll
        for (int j = 0; j < 4; ++j) acc[i][j] = 0.f;

    {
        float4 a0 = *(const float4*)&A[(size_t)(m0 + ar0) * D_DIM + ac0];
        float4 a1 = *(const float4*)&A[(size_t)(m0 + ar1) * D_DIM + ac1];
        float4 b0 = *(const float4*)&W[(size_t)br0 * D_DIM + n0 + bc0];
        float4 b1 = *(const float4*)&W[(size_t)br1 * D_DIM + n0 + bc1];
        As[0][ar0][ac0 + 0] = a0.x; As[0][ar0][ac0 + 1] = a0.y;
        As[0][ar0][ac0 + 2] = a0.z; As[0][ar0][ac0 + 3] = a0.w;
        As[0][ar1][ac1 + 0] = a1.x; As[0][ar1][ac1 + 1] = a1.y;
        As[0][ar1][ac1 + 2] = a1.z; As[0][ar1][ac1 + 3] = a1.w;
        *(float4*)&Bs[0][br0][bc0] = b0;
        *(float4*)&Bs[0][br1][bc1] = b1;
    }
    __syncthreads();

    int buf = 0;
    for (int k0 = 0; k0 < D_DIM; k0 += 32) {
        const bool has_next = (k0 + 32) < D_DIM;
        float4 a0, a1, b0, b1;
        if (has_next) {
            const int kn = k0 + 32;
            a0 = *(const float4*)&A[(size_t)(m0 + ar0) * D_DIM + kn + ac0];
            a1 = *(const float4*)&A[(size_t)(m0 + ar1) * D_DIM + kn + ac1];
            b0 = *(const float4*)&W[(size_t)(kn + br0) * D_DIM + n0 + bc0];
            b1 = *(const float4*)&W[(size_t)(kn + br1) * D_DIM + n0 + bc1];
        }

#pragma unroll
        for (int k = 0; k < 32; ++k) {
            float4 b4 = *(const float4*)&Bs[buf][k][tx * 4];
            float x0 = As[buf][ty * 4 + 0][k];
            float x1 = As[buf][ty * 4 + 1][k];
            float x2 = As[buf][ty * 4 + 2][k];
            float x3 = As[buf][ty * 4 + 3][k];
            acc[0][0] += x0 * b4.x; acc[0][1] += x0 * b4.y; acc[0][2] += x0 * b4.z; acc[0][3] += x0 * b4.w;
            acc[1][0] += x1 * b4.x; acc[1][1] += x1 * b4.y; acc[1][2] += x1 * b4.z; acc[1][3] += x1 * b4.w;
            acc[2][0] += x2 * b4.x; acc[2][1] += x2 * b4.y; acc[2][2] += x2 * b4.z; acc[2][3] += x2 * b4.w;
            acc[3][0] += x3 * b4.x; acc[3][1] += x3 * b4.y; acc[3][2] += x3 * b4.z; acc[3][3] += x3 * b4.w;
        }

        if (has_next) {
            const int nb = buf ^ 1;
            As[nb][ar0][ac0 + 0] = a0.x; As[nb][ar0][ac0 + 1] = a0.y;
            As[nb][ar0][ac0 + 2] = a0.z; As[nb][ar0][ac0 + 3] = a0.w;
            As[nb][ar1][ac1 + 0] = a1.x; As[nb][ar1][ac1 + 1] = a1.y;
            As[nb][ar1][ac1 + 2] = a1.z; As[nb][ar1][ac1 + 3] = a1.w;
            *(float4*)&Bs[nb][br0][bc0] = b0;
            *(float4*)&Bs[nb][br1][bc1] = b1;
        }
        __syncthreads();
        buf ^= 1;
    }

#pragma unroll
    for (int i = 0; i < 4; ++i) {
        int m = m0 + ty * 4 + i;
        int bb = m & (B_DIM - 1);
        int tt = m >> 4;
        const float b0 = bias[n0 + tx * 4 + 0];
        const float b1 = bias[n0 + tx * 4 + 1];
        const float b2 = bias[n0 + tx * 4 + 2];
        const float b3 = bias[n0 + tx * 4 + 3];
        __half2 h2[2];
        h2[0] = __floats2half2_rn(acc[i][0] + b0, acc[i][1] + b1);
        h2[1] = __floats2half2_rn(acc[i][2] + b2, acc[i][3] + b3);
        __half2* dst = &g_h16[(((size_t)bb * T_DIM + tt) * D_DIM + n0 + tx * 4) / 2];
        *(uint2*)dst = *(const uint2*)h2;
    }
}

// ---------------------------------------------------------------------------
// Kernel 2: logits + softmax. grid=(B, T/2)=512 blocks, 512 thr, 2 CTA/SM.
// Warp w owns full D (16 dims/lane as 8 half2) and 16 s values.
// ---------------------------------------------------------------------------
__global__ __launch_bounds__(512, 2) void logits_kernel(
    const float* __restrict__ v_w,       // (D) fp32
    float* __restrict__ out_attn)        // (B*T, S) -> normalized probs
{
    __shared__ float lg[T_TILE][S_DIM];  // 2 KB

    const int b    = blockIdx.x;
    const int t0   = blockIdx.y * T_TILE;
    const int tid  = threadIdx.x;
    const int wid  = tid >> 5;
    const int lane = tid & 31;

    __half2 hh[T_TILE][8];
    __half2 ww[8];
    {
        const uint4* hp = (const uint4*)(g_h16 + ((size_t)b * T_DIM + t0) * (D_DIM / 2));
#pragma unroll
        for (int t = 0; t < T_TILE; ++t) {
            uint4 u0 = hp[t * (D_DIM / 8) + lane * 2];
            uint4 u1 = hp[t * (D_DIM / 8) + lane * 2 + 1];
            *(uint4*)&hh[t][0] = u0;
            *(uint4*)&hh[t][4] = u1;
        }
        const float4* vw4 = (const float4*)v_w;
#pragma unroll
        for (int j = 0; j < 4; ++j) {
            float4 w = vw4[lane * 4 + j];
            ww[j * 2 + 0] = __floats2half2_rn(w.x, w.y);
            ww[j * 2 + 1] = __floats2half2_rn(w.z, w.w);
        }
    }

    {
        const uint4* cbase = (const uint4*)(g_c16 + (size_t)b * S_DIM * (D_DIM / 2))
                             + (size_t)(wid * 16) * (D_DIM / 8) + lane * 2;
        uint4 cu0 = cbase[0];
        uint4 cu1 = cbase[1];

        for (int si = 0; si < 16; ++si) {
            uint4 nu0, nu1;
            if (si < 15) {
                nu0 = cbase[(si + 1) * (D_DIM / 8)];
                nu1 = cbase[(si + 1) * (D_DIM / 8) + 1];
            }
            __half2 cc[8];
            *(uint4*)&cc[0] = cu0;
            *(uint4*)&cc[4] = cu1;

            float acc[T_TILE];
#pragma unroll
            for (int t = 0; t < T_TILE; ++t) {
                __half2 p[8];
#pragma unroll
                for (int j = 0; j < 8; ++j)
                    p[j] = __hmul2(tanh2_ap(__hadd2(hh[t][j], cc[j])), ww[j]);
                __half2 q0 = __hadd2(p[0], p[1]);
                __half2 q1 = __hadd2(p[2], p[3]);
                __half2 q2 = __hadd2(p[4], p[5]);
                __half2 q3 = __hadd2(p[6], p[7]);
                float a = (__low2float(q0) + __high2float(q0))
                        + (__low2float(q1) + __high2float(q1));
                float c = (__low2float(q2) + __high2float(q2))
                        + (__low2float(q3) + __high2float(q3));
                acc[t] = a + c;
            }

            float r0 = acc[0] + __shfl_xor_sync(0xffffffffu, acc[0], 16);
            float r1 = acc[1] + __shfl_xor_sync(0xffffffffu, acc[1], 16);
            float m = (lane & 16) ? r1 : r0;
            m += __shfl_xor_sync(0xffffffffu, m, 8);
            m += __shfl_xor_sync(0xffffffffu, m, 4);
            m += __shfl_xor_sync(0xffffffffu, m, 2);
            m += __shfl_xor_sync(0xffffffffu, m, 1);
            if ((lane & 15) == 0)
                lg[lane >> 4][wid * 16 + si] = m;

            cu0 = nu0; cu1 = nu1;
        }
    }
    __syncthreads();

    if (wid < T_TILE) {
        const int t = wid;
        float e[8];
        float m = -1e30f;
#pragma unroll
        for (int k = 0; k < 8; ++k) {
            e[k] = lg[t][k * 32 + lane];
            m = fmaxf(m, e[k]);
        }
#pragma unroll
        for (int o = 16; o; o >>= 1) m = fmaxf(m, __shfl_xor_sync(0xffffffffu, m, o));
        float ssum = 0.f;
#pragma unroll
        for (int k = 0; k < 8; ++k) {
            e[k] = __expf(e[k] - m);
            ssum += e[k];
        }
#pragma unroll
        for (int o = 16; o; o >>= 1) ssum += __shfl_xor_sync(0xffffffffu, ssum, o);
        const float inv = 1.0f / ssum;
        float* oa = out_attn + ((size_t)b * T_DIM + t0 + t) * S_DIM;
#pragma unroll
        for (int k = 0; k < 8; ++k)
            oa[k * 32 + lane] = e[k] * inv;
    }
}

// ---------------------------------------------------------------------------
// Kernel 3: weighted = attn @ values, SMEM-staged double-buffered tiles.
// grid=(B, 2, T/8)=256 blocks, 256 thr, 2 CTA/SM (smem 40KB/block).
// Stage = 16 s x 256 d of values (16KB) loaded cooperatively (4 float4/thr).
// Compute: thread (tx=d-float4, ty=t-pair), per s: 1 LDS128 + 2 LDS + 8 FFMA.
// ---------------------------------------------------------------------------
__global__ __launch_bounds__(256, 2) void av_kernel(
    const float* __restrict__ values,    // (B,S,D)
    const float* __restrict__ attn,      // (B*T, S) normalized
    float* __restrict__ out_w)           // (T,B,D)
{
    __shared__ float p_s[T_AV][S_DIM];   // 8 KB
    __shared__ float4 vs[2][16][64];     // 32 KB

    const int b   = blockIdx.x;
    const int dh  = blockIdx.y;
    const int t0  = blockIdx.z * T_AV;
    const int tid = threadIdx.x;
    const int tx  = tid & 63;            // d float4 column (0..63)
    const int ty  = tid >> 6;            // 0..3 -> t pair (t = ty*2, ty*2+1)

    // stage probs
    {
        const float4* ap = (const float4*)(attn + ((size_t)b * T_DIM + t0) * S_DIM);
        float4* ps4 = (float4*)p_s;
        for (int i = tid; i < T_AV * S_DIM / 4; i += 256) ps4[i] = ap[i];
    }

    // values base for this (b, d-half), in float4 units; row stride = 128
    const float4* vp = (const float4*)(values + (size_t)b * S_DIM * D_DIM + dh * 256);
    const int r0 = tid >> 6;             // staging row within group (0..3)

    float acc[2][4];
#pragma unroll
    for (int i = 0; i < 2; ++i)
#pragma unroll
        for (int j = 0; j < 4; ++j) acc[i][j] = 0.f;

    // preload stage 0 (rows r0, r0+4, r0+8, r0+12)
    float4 pre[4];
#pragma unroll
    for (int k = 0; k < 4; ++k)
        pre[k] = vp[(size_t)(r0 + k * 4) * (D_DIM / 4) + tx];
#pragma unroll
    for (int k = 0; k < 4; ++k)
        vs[0][r0 + k * 4][tx] = pre[k];
    __syncthreads();

    int buf = 0;
    for (int s0 = 0; s0 < S_DIM; s0 += 16) {
        const bool hn = (s0 + 16) < S_DIM;
        if (hn) {
#pragma unroll
            for (int k = 0; k < 4; ++k)
                pre[k] = vp[(size_t)(s0 + 16 + r0 + k * 4) * (D_DIM / 4) + tx];
        }

#pragma unroll
        for (int s = 0; s < 16; ++s) {
            float4 v = vs[buf][s][tx];
            float pa = p_s[ty * 2 + 0][s0 + s];
            float pb = p_s[ty * 2 + 1][s0 + s];
            acc[0][0] += pa * v.x; acc[0][1] += pa * v.y;
            acc[0][2] += pa * v.z; acc[0][3] += pa * v.w;
            acc[1][0] += pb * v.x; acc[1][1] += pb * v.y;
            acc[1][2] += pb * v.z; acc[1][3] += pb * v.w;
        }

        if (hn) {
            const int nb = buf ^ 1;
#pragma unroll
            for (int k = 0; k < 4; ++k)
                vs[nb][r0 + k * 4][tx] = pre[k];
        }
        __syncthreads();
        buf ^= 1;
    }

#pragma unroll
    for (int i = 0; i < 2; ++i) {
        const int t = ty * 2 + i;
        float4 o;
        o.x = acc[i][0]; o.y = acc[i][1]; o.z = acc[i][2]; o.w = acc[i][3];
        *(float4*)&out_w[((size_t)(t0 + t) * B_DIM + b) * D_DIM + dh * 256 + tx * 4] = o;
    }
}

// ---------------------------------------------------------------------------
extern "C" void kernel_launch(void* const* d_in, const int* in_sizes, int n_in,
                              void* d_out, int out_size) {
    const float* input   = (const float*)d_in[0];
    const float* context = (const float*)d_in[1];
    const float* values  = (const float*)d_in[2];
    const float* W_comb  = (const float*)d_in[3];
    const float* b_comb  = (const float*)d_in[4];
    const float* v_w     = (const float*)d_in[5];

    float* out_weighted = (float*)d_out;                                 // (T,B,D)
    float* out_attn     = (float*)d_out + (size_t)T_DIM * B_DIM * D_DIM; // (B*T,S)

    const int conv_blocks = (B_DIM * S_DIM * D_DIM / 8) / 256;           // 1024
    conv_kernel<<<conv_blocks, 256>>>(context);

    dim3 g1(D_DIM / 64, (T_DIM * B_DIM) / 64);           // (8,16)
    gemm_kernel<<<g1, 256>>>(input, W_comb, b_comb);

    dim3 g2(B_DIM, T_DIM / T_TILE);                      // (16,32) = 512 blocks
    logits_kernel<<<g2, 512>>>(v_w, out_attn);

    dim3 g3(B_DIM, 2, T_DIM / T_AV);                     // (16,2,8) = 256 blocks
    av_kernel<<<g3, 256>>>(values, out_attn, out_weighted);
}